// round 17
// baseline (speedup 1.0000x reference)
#include <cuda_runtime.h>
#include <cuda_fp16.h>
#include <stdint.h>

// MessageFunction via mma.sync m16n8k16 fp16 (fp32 accum), persistent CTAs.
// R17: R16 base + algebraic issue-slot cuts:
//      (1) b2 folded into GEMM2 accumulator INIT (acc starts at bias);
//      (2) b1 folded into GEMM1 accumulator INIT;
//      (3) scalar-FFMA matvec epilogue (same FMA count as packed f32x2,
//          zero pk2/losum packing overhead).

#define TPB   256
#define TILE  256
#define ESTR  20
#define HSTR  20

// ---- smem float offsets (per CTA 77056 bytes) ----
#define OF_W2F 0       // 8192 fl: W2 B-frag PAIRS uint4[ks(4)][pair(16)][lane(32)]
#define OF_W1F 8192    // 512 fl : W1 B-frag PAIRS uint4[pair(4)][lane(32)]
#define OF_B1  8704    // 64
#define OF_B2  8768    // 256
#define OF_E   9024    // 5120 fl : e tile f32 [256][stride 20]
#define OF_H   14144   // 5120 fl : h tile f32 [256][stride 20]
#define SMEM_FLOATS 19264   // 77056 bytes

__device__ __forceinline__ uint32_t pack_h2(float a, float b) {
    __half2 h = __floats2half2_rn(a, b);
    return *(uint32_t*)&h;
}
__device__ __forceinline__ uint32_t smem_u32(const void* p) {
    uint32_t a;
    asm("{ .reg .u64 t; cvta.to.shared.u64 t, %1; cvt.u32.u64 %0, t; }" : "=r"(a) : "l"(p));
    return a;
}

// Not volatile: pure register computation; let ptxas pipeline it.
#define MMA_F16(d, a, b0, b1) \
    asm("mma.sync.aligned.m16n8k16.row.col.f32.f16.f16.f32 " \
        "{%0,%1,%2,%3}, {%4,%5,%6,%7}, {%8,%9}, {%0,%1,%2,%3};" \
        : "+f"((d)[0]), "+f"((d)[1]), "+f"((d)[2]), "+f"((d)[3]) \
        : "r"((a)[0]), "r"((a)[1]), "r"((a)[2]), "r"((a)[3]), \
          "r"(b0), "r"(b1))

__device__ __forceinline__ void red_add_v4(float* p, float a, float b,
                                           float c, float d) {
    asm volatile("red.global.add.v4.f32 [%0], {%1,%2,%3,%4};"
                 :: "l"(p), "f"(a), "f"(b), "f"(c), "f"(d) : "memory");
}
__device__ __forceinline__ void cp16(uint32_t s, const void* g) {
    asm volatile("cp.async.cg.shared.global [%0], [%1], 16;" :: "r"(s), "l"(g));
}
__device__ __forceinline__ void cp_commit() {
    asm volatile("cp.async.commit_group;" ::: "memory");
}
__device__ __forceinline__ void cp_wait_all() {
    asm volatile("cp.async.wait_group 0;" ::: "memory");
}

extern "C" __global__ void __launch_bounds__(TPB, 2)
msg_mma_kernel(const int* __restrict__ index_v,
               const float* __restrict__ h_w,
               const float* __restrict__ e_vw,
               const float* __restrict__ W1,
               const float* __restrict__ b1,
               const float* __restrict__ W2,
               const float* __restrict__ b2,
               float* __restrict__ out,
               int n_edge) {
    extern __shared__ float sm[];
    const uint32_t sb = smem_u32(sm);
    const int tid  = threadIdx.x;
    const int warp = tid >> 5;
    const int lane = tid & 31;
    const int q = lane & 3;       // quad col
    const int g = lane >> 2;      // group row

    // ================= stage weight fragments (once per CTA) =================
    // W2 B-frag pairs: uint4 { frag(2p).x, frag(2p).y, frag(2p+1).x, frag(2p+1).y }
    for (int s = tid; s < 2048; s += TPB) {
        int ks = s >> 9, p = (s >> 5) & 15, ln = s & 31;
        int qq = ln & 3, gg = ln >> 2;
        int r0 = ks * 16 + 2 * qq;
        uint4 u;
        {
            int n = (2 * p) * 8 + gg;
            u.x = pack_h2(W2[(r0)     * 256 + n], W2[(r0 + 1) * 256 + n]);
            u.y = pack_h2(W2[(r0 + 8) * 256 + n], W2[(r0 + 9) * 256 + n]);
        }
        {
            int n = (2 * p + 1) * 8 + gg;
            u.z = pack_h2(W2[(r0)     * 256 + n], W2[(r0 + 1) * 256 + n]);
            u.w = pack_h2(W2[(r0 + 8) * 256 + n], W2[(r0 + 9) * 256 + n]);
        }
        ((uint4*)(sm + OF_W2F))[s] = u;
    }
    // W1 B-frag pairs
    for (int s = tid; s < 128; s += TPB) {
        int p = s >> 5, ln = s & 31;
        int qq = ln & 3, gg = ln >> 2;
        uint4 u;
        {
            int n = (2 * p) * 8 + gg;
            u.x = pack_h2(W1[(2 * qq)     * 64 + n], W1[(2 * qq + 1) * 64 + n]);
            u.y = pack_h2(W1[(2 * qq + 8) * 64 + n], W1[(2 * qq + 9) * 64 + n]);
        }
        {
            int n = (2 * p + 1) * 8 + gg;
            u.z = pack_h2(W1[(2 * qq)     * 64 + n], W1[(2 * qq + 1) * 64 + n]);
            u.w = pack_h2(W1[(2 * qq + 8) * 64 + n], W1[(2 * qq + 9) * 64 + n]);
        }
        ((uint4*)(sm + OF_W1F))[s] = u;
    }
    if (tid < 64)  sm[OF_B1 + tid] = b1[tid];
    if (tid < 256) sm[OF_B2 + tid] = b2[tid];

    const int ntiles = (n_edge + TILE - 1) / TILE;

    // ---- async stage of tile t: thread tid owns row tid (warp-private) ----
    auto stage = [&](int t) {
        const int base = t * TILE;
        const int rem  = n_edge - base;
        const int sr   = tid < rem ? tid : rem - 1;
        const char* ep = (const char*)(e_vw + (size_t)(base + sr) * 16);
        const char* hp = (const char*)(h_w  + (size_t)(base + sr) * 16);
        const uint32_t de = sb + (OF_E + tid * ESTR) * 4;
        const uint32_t dh = sb + (OF_H + tid * HSTR) * 4;
#pragma unroll
        for (int i = 0; i < 4; i++) {
            cp16(de + 16 * i, ep + 16 * i);
            cp16(dh + 16 * i, hp + 16 * i);
        }
        cp_commit();
    };

    __syncthreads();   // weights visible CTA-wide (E/H are warp-private)

    // ---- prologue ----
    if (blockIdx.x < ntiles) stage(blockIdx.x);

    for (int t = blockIdx.x; t < ntiles; t += gridDim.x) {
        const int base = t * TILE;

        cp_wait_all();     // this warp's rows landed
        __syncwarp();      // cross-lane smem visibility within the warp

        // ---- GEMM1 in two 16-row passes; build A-frags ha[2][4][4].
        //      b1 folded into accumulator INIT (acc starts at bias). ----
        uint32_t ha[2][4][4];
#pragma unroll
        for (int p = 0; p < 2; p++) {
            const int r0 = warp * 32 + p * 16 + g;
            const float* Er = sm + OF_E + r0 * ESTR;
            uint32_t ea[4];
            {
                float2 c0 = *(const float2*)(Er + 2 * q);
                float2 c1 = *(const float2*)(Er + 8 * ESTR + 2 * q);
                float2 c2 = *(const float2*)(Er + 8 + 2 * q);
                float2 c3 = *(const float2*)(Er + 8 * ESTR + 8 + 2 * q);
                ea[0] = pack_h2(c0.x, c0.y);
                ea[1] = pack_h2(c1.x, c1.y);
                ea[2] = pack_h2(c2.x, c2.y);
                ea[3] = pack_h2(c3.x, c3.y);
            }
            float acc1[8][4];
#pragma unroll
            for (int nt = 0; nt < 8; nt++) {
                float2 bb = *(const float2*)(sm + OF_B1 + nt * 8 + 2 * q);
                acc1[nt][0] = bb.x; acc1[nt][1] = bb.y;
                acc1[nt][2] = bb.x; acc1[nt][3] = bb.y;
            }
#pragma unroll
            for (int p2 = 0; p2 < 4; p2++) {
                uint4 u = ((const uint4*)(sm + OF_W1F))[p2 * 32 + lane];
                MMA_F16(acc1[2 * p2],     ea, u.x, u.y);
                MMA_F16(acc1[2 * p2 + 1], ea, u.z, u.w);
            }
#pragma unroll
            for (int nt = 0; nt < 8; nt++) {
                float v0 = fmaxf(acc1[nt][0], 0.0f);
                float v1 = fmaxf(acc1[nt][1], 0.0f);
                float v2 = fmaxf(acc1[nt][2], 0.0f);
                float v3 = fmaxf(acc1[nt][3], 0.0f);
                int ks = nt >> 1, hi = (nt & 1) * 2;
                ha[p][ks][hi]     = pack_h2(v0, v1);   // row g
                ha[p][ks][hi + 1] = pack_h2(v2, v3);   // row g+8
            }
        }

        // ---- h regs + nodes (warp-private rows) ----
        float hreg[2][2][4];
        int   node[2][2];
        bool  vld[2][2];
#pragma unroll
        for (int mt = 0; mt < 2; mt++)
#pragma unroll
            for (int rr = 0; rr < 2; rr++) {
                const int row = warp * 32 + mt * 16 + g + rr * 8;
                const float* Hr = sm + OF_H + row * HSTR;
                float2 h0 = *(const float2*)(Hr + 2 * q);
                float2 h1 = *(const float2*)(Hr + 8 + 2 * q);
                hreg[mt][rr][0] = h0.x; hreg[mt][rr][1] = h0.y;
                hreg[mt][rr][2] = h1.x; hreg[mt][rr][3] = h1.y;
                const int ge = base + row;
                vld[mt][rr]  = ge < n_edge;
                node[mt][rr] = vld[mt][rr] ? __ldg(index_v + ge) : 0;
            }

        // ---- all E/H reads done for this warp: stage next tile now ----
        __syncwarp();
        const int tn = t + gridDim.x;
        if (tn < ntiles) stage(tn);

        // ---- GEMM2 + epilogue, 8 chunks of 32 cols (m = 2c, 2c+1).
        //      b2 folded into accumulator INIT. Scalar FFMA matvec.
        //      Even chunk buffers its reduced m-pair; odd chunk emits red.v4.
        float vbuf[2][2][2];
#pragma unroll
        for (int c = 0; c < 8; c++) {
            float acc[2][4][4];
#pragma unroll
            for (int nt = 0; nt < 4; nt++) {
                const int ntg = c * 4 + nt;
                float2 bb = *(const float2*)(sm + OF_B2 + ntg * 8 + 2 * q);
#pragma unroll
                for (int mt = 0; mt < 2; mt++) {
                    acc[mt][nt][0] = bb.x; acc[mt][nt][1] = bb.y;
                    acc[mt][nt][2] = bb.x; acc[mt][nt][3] = bb.y;
                }
            }
#pragma unroll
            for (int ks = 0; ks < 4; ks++)
#pragma unroll
                for (int pp = 0; pp < 2; pp++) {
                    // pair pp covers ntg = c*4 + 2pp, c*4 + 2pp + 1
                    uint4 u = ((const uint4*)(sm + OF_W2F))[(ks * 16 + c * 2 + pp) * 32 + lane];
                    MMA_F16(acc[0][2 * pp],     ha[0][ks], u.x, u.y);
                    MMA_F16(acc[1][2 * pp],     ha[1][ks], u.x, u.y);
                    MMA_F16(acc[0][2 * pp + 1], ha[0][ks], u.z, u.w);
                    MMA_F16(acc[1][2 * pp + 1], ha[1][ks], u.z, u.w);
                }
            // ---- scalar FFMA matvec: pacc += acc * h ----
            float pacc[2][2][2];
#pragma unroll
            for (int mt = 0; mt < 2; mt++)
#pragma unroll
                for (int rr = 0; rr < 2; rr++) {
                    pacc[mt][rr][0] = 0.0f; pacc[mt][rr][1] = 0.0f;
                }
#pragma unroll
            for (int nt = 0; nt < 4; nt++) {
                const int hb = (nt & 1) * 2;
                const int ml = nt >> 1;
#pragma unroll
                for (int mt = 0; mt < 2; mt++) {
                    pacc[mt][0][ml] = fmaf(acc[mt][nt][0], hreg[mt][0][hb],     pacc[mt][0][ml]);
                    pacc[mt][0][ml] = fmaf(acc[mt][nt][1], hreg[mt][0][hb + 1], pacc[mt][0][ml]);
                    pacc[mt][1][ml] = fmaf(acc[mt][nt][2], hreg[mt][1][hb],     pacc[mt][1][ml]);
                    pacc[mt][1][ml] = fmaf(acc[mt][nt][3], hreg[mt][1][hb + 1], pacc[mt][1][ml]);
                }
            }
#pragma unroll
            for (int mt = 0; mt < 2; mt++)
#pragma unroll
                for (int rr = 0; rr < 2; rr++) {
#pragma unroll
                    for (int ml = 0; ml < 2; ml++) {
                        float v = pacc[mt][rr][ml];
                        v += __shfl_xor_sync(0xFFFFFFFFu, v, 1);
                        v += __shfl_xor_sync(0xFFFFFFFFu, v, 2);
                        pacc[mt][rr][ml] = v;
                    }
                    if ((c & 1) == 0) {
                        vbuf[mt][rr][0] = pacc[mt][rr][0];
                        vbuf[mt][rr][1] = pacc[mt][rr][1];
                    } else if (q == 0 && vld[mt][rr]) {
                        red_add_v4(out + (size_t)node[mt][rr] * 16 + 2 * (c - 1),
                                   vbuf[mt][rr][0], vbuf[mt][rr][1],
                                   pacc[mt][rr][0], pacc[mt][rr][1]);
                    }
                }
        }
        // no __syncthreads: E/H rows are warp-private; pipeline is per-warp
    }
}

// ---------------- launch ----------------
extern "C" void kernel_launch(void* const* d_in, const int* in_sizes, int n_in,
                              void* d_out, int out_size) {
    const int*   index_v = nullptr;
    const float* h_w = nullptr;
    const float* e_vw = nullptr;
    const float* W1 = nullptr;
    const float* b1 = nullptr;
    const float* W2 = nullptr;
    const float* b2 = nullptr;

    int big_idx[8]; long long big_sz[8]; int nb = 0;
    for (int i = 0; i < n_in; i++) {
        long long s = in_sizes[i];
        if (s == 1024)       W1 = (const float*)d_in[i];
        else if (s == 64)    b1 = (const float*)d_in[i];
        else if (s == 16384) W2 = (const float*)d_in[i];
        else if (s == 256)   b2 = (const float*)d_in[i];
        else if (s > 100000 && nb < 8) { big_idx[nb] = i; big_sz[nb] = s; nb++; }
    }
    long long min_sz = big_sz[0]; int min_pos = 0;
    for (int i = 1; i < nb; i++)
        if (big_sz[i] < min_sz) { min_sz = big_sz[i]; min_pos = i; }
    index_v = (const int*)d_in[big_idx[min_pos]];
    int n_edge = (int)min_sz;
    bool got_h = false;
    for (int i = 0; i < nb; i++) {
        if (i == min_pos) continue;
        if (!got_h) { h_w = (const float*)d_in[big_idx[i]]; got_h = true; }
        else        { e_vw = (const float*)d_in[big_idx[i]]; }
    }

    float* out = (float*)d_out;
    cudaMemsetAsync(out, 0, (size_t)out_size * sizeof(float));

    static bool attr_set = false;
    if (!attr_set) {
        cudaFuncSetAttribute(msg_mma_kernel,
                             cudaFuncAttributeMaxDynamicSharedMemorySize,
                             SMEM_FLOATS * (int)sizeof(float));
        attr_set = true;
    }
    int ntiles = (n_edge + TILE - 1) / TILE;
    int grid = ntiles < 304 ? ntiles : 304;   // 2 CTAs/SM x 152 SMs
    msg_mma_kernel<<<grid, TPB, SMEM_FLOATS * sizeof(float)>>>(
        index_v, h_w, e_vw, W1, b1, W2, b2, out, n_edge);
}